// round 2
// baseline (speedup 1.0000x reference)
#include <cuda_runtime.h>

// Problem dims
#define BB 8
#define CC 512
#define TT 2048
#define EE 512
#define LN_EPS 1e-5f

// ---------------- scratch (device globals: allocation-free rule) ----------------
__device__ float g_resid[BB * TT * CC];  // [B,T,C] residual (transposed x)
__device__ float g_q[BB * TT * EE];
__device__ float g_k[BB * TT * EE];
__device__ float g_v[BB * TT * EE];
__device__ float g_att[BB * TT * EE];    // attended [B,T,E]
// h (pre-LN) reuses g_q after energy GEMM no longer needs q? q IS needed only for
// energy which happens before proj -> safe to reuse g_q as h.

// ---------------- transpose: x[B,C,T] -> resid[B,T,C] ----------------
__global__ __launch_bounds__(256)
void transpose_kernel(const float* __restrict__ x, float* __restrict__ r) {
    __shared__ float tile[32][33];
    int b = blockIdx.z;
    int t0 = blockIdx.x * 32;
    int c0 = blockIdx.y * 32;
    const float* xb = x + (size_t)b * CC * TT;
    float* rb = r + (size_t)b * TT * CC;
    int tx = threadIdx.x, ty = threadIdx.y;  // 32 x 8
#pragma unroll
    for (int i = ty; i < 32; i += 8)
        tile[i][tx] = xb[(size_t)(c0 + i) * TT + t0 + tx];
    __syncthreads();
#pragma unroll
    for (int i = ty; i < 32; i += 8)
        rb[(size_t)(t0 + i) * CC + c0 + tx] = tile[tx][i];
}

// ---------------- SGEMM: 128x128x8 tile, 256 threads, 8x8 microtile ----------------
// C[m,n] = sum_k A[m,k] * B'[k,n]   (B' = B  if !TRANSB, B' = B^T if TRANSB, B row-major [N,K])
// EPI: 0 = plain store, 1 = +bias[n], 2 = +bias[n] + res[m,n]
template <bool TRANSB, int EPI>
__global__ __launch_bounds__(256)
void sgemm(const float* __restrict__ Ag, const float* __restrict__ Bg,
           const float* __restrict__ bias, const float* __restrict__ resg,
           float* __restrict__ Cg,
           int K, int lda, int ldb, int ldc,
           size_t sA, size_t sB, size_t sC) {
    const float* A = Ag + (size_t)blockIdx.z * sA;
    const float* Bm = Bg + (size_t)blockIdx.z * sB;
    float* Cc = Cg + (size_t)blockIdx.z * sC;
    const float* res = (EPI == 2) ? (resg + (size_t)blockIdx.z * sC) : nullptr;

    const int bm = blockIdx.y * 128;
    const int bn = blockIdx.x * 128;
    const int tid = threadIdx.x;
    const int tx = tid & 15;       // 0..15  -> N
    const int ty = tid >> 4;       // 0..15  -> M

    __shared__ float As[8][128];
    __shared__ float Bs[8][128];

    float acc[8][8];
#pragma unroll
    for (int i = 0; i < 8; i++)
#pragma unroll
        for (int j = 0; j < 8; j++) acc[i][j] = 0.f;

    // A tile load mapping: 128 rows x 8 k, 256 threads -> 1 float4 each
    const int arow = tid >> 1;
    const int akg = (tid & 1) * 4;

    for (int k0 = 0; k0 < K; k0 += 8) {
        float4 va = *(const float4*)(A + (size_t)(bm + arow) * lda + k0 + akg);
        float4 vb;
        int bn_idx = 0, bkg = 0, brw = 0, bcl = 0;
        if (TRANSB) {
            bn_idx = tid >> 1;            // 0..127 (N)
            bkg = (tid & 1) * 4;          // 0 or 4 (K)
            vb = *(const float4*)(Bm + (size_t)(bn + bn_idx) * ldb + k0 + bkg);
        } else {
            brw = tid >> 5;               // 0..7 (K)
            bcl = (tid & 31) * 4;         // 0..124 (N)
            vb = *(const float4*)(Bm + (size_t)(k0 + brw) * ldb + bn + bcl);
        }
        __syncthreads();  // previous compute done before overwriting smem
        As[akg + 0][arow] = va.x;
        As[akg + 1][arow] = va.y;
        As[akg + 2][arow] = va.z;
        As[akg + 3][arow] = va.w;
        if (TRANSB) {
            Bs[bkg + 0][bn_idx] = vb.x;
            Bs[bkg + 1][bn_idx] = vb.y;
            Bs[bkg + 2][bn_idx] = vb.z;
            Bs[bkg + 3][bn_idx] = vb.w;
        } else {
            *(float4*)&Bs[brw][bcl] = vb;
        }
        __syncthreads();

#pragma unroll
        for (int k = 0; k < 8; k++) {
            float4 a0 = *(const float4*)&As[k][ty * 8];
            float4 a1 = *(const float4*)&As[k][ty * 8 + 4];
            float4 b0 = *(const float4*)&Bs[k][tx * 8];
            float4 b1 = *(const float4*)&Bs[k][tx * 8 + 4];
            float af[8] = {a0.x, a0.y, a0.z, a0.w, a1.x, a1.y, a1.z, a1.w};
            float bf[8] = {b0.x, b0.y, b0.z, b0.w, b1.x, b1.y, b1.z, b1.w};
#pragma unroll
            for (int i = 0; i < 8; i++)
#pragma unroll
                for (int j = 0; j < 8; j++) acc[i][j] += af[i] * bf[j];
        }
    }

    // epilogue
#pragma unroll
    for (int i = 0; i < 8; i++) {
        int row = bm + ty * 8 + i;
        float* crow = Cc + (size_t)row * ldc + bn + tx * 8;
        const float* rrow = (EPI == 2) ? (res + (size_t)row * ldc + bn + tx * 8) : nullptr;
#pragma unroll
        for (int j = 0; j < 8; j += 4) {
            float4 v;
            v.x = acc[i][j + 0];
            v.y = acc[i][j + 1];
            v.z = acc[i][j + 2];
            v.w = acc[i][j + 3];
            if (EPI >= 1) {
                const float* bp = bias + bn + tx * 8 + j;
                v.x += bp[0]; v.y += bp[1]; v.z += bp[2]; v.w += bp[3];
            }
            if (EPI == 2) {
                v.x += rrow[j + 0]; v.y += rrow[j + 1];
                v.z += rrow[j + 2]; v.w += rrow[j + 3];
            }
            *(float4*)(crow + j) = v;
        }
    }
}

// ---------------- row softmax over T=2048, in place ----------------
__global__ __launch_bounds__(256)
void softmax_kernel(float* __restrict__ attn) {
    float* row = attn + (size_t)blockIdx.x * TT;
    int t = threadIdx.x;
    float4 v0 = ((float4*)row)[2 * t];
    float4 v1 = ((float4*)row)[2 * t + 1];

    float m = fmaxf(fmaxf(fmaxf(v0.x, v0.y), fmaxf(v0.z, v0.w)),
                    fmaxf(fmaxf(v1.x, v1.y), fmaxf(v1.z, v1.w)));
#pragma unroll
    for (int o = 16; o; o >>= 1) m = fmaxf(m, __shfl_xor_sync(0xffffffffu, m, o));
    __shared__ float smax[8];
    __shared__ float ssum[8];
    if ((t & 31) == 0) smax[t >> 5] = m;
    __syncthreads();
    float rm = smax[0];
#pragma unroll
    for (int i = 1; i < 8; i++) rm = fmaxf(rm, smax[i]);

    v0.x = expf(v0.x - rm); v0.y = expf(v0.y - rm);
    v0.z = expf(v0.z - rm); v0.w = expf(v0.w - rm);
    v1.x = expf(v1.x - rm); v1.y = expf(v1.y - rm);
    v1.z = expf(v1.z - rm); v1.w = expf(v1.w - rm);

    float s = v0.x + v0.y + v0.z + v0.w + v1.x + v1.y + v1.z + v1.w;
#pragma unroll
    for (int o = 16; o; o >>= 1) s += __shfl_xor_sync(0xffffffffu, s, o);
    if ((t & 31) == 0) ssum[t >> 5] = s;
    __syncthreads();
    float total = 0.f;
#pragma unroll
    for (int i = 0; i < 8; i++) total += ssum[i];
    float inv = 1.f / total;

    v0.x *= inv; v0.y *= inv; v0.z *= inv; v0.w *= inv;
    v1.x *= inv; v1.y *= inv; v1.z *= inv; v1.w *= inv;
    ((float4*)row)[2 * t] = v0;
    ((float4*)row)[2 * t + 1] = v1;
}

// ---------------- LayerNorm over C=512 ----------------
__global__ __launch_bounds__(128)
void ln_kernel(const float* __restrict__ h, const float* __restrict__ gamma,
               const float* __restrict__ beta, float* __restrict__ out) {
    const float* hr = h + (size_t)blockIdx.x * CC;
    int t = threadIdx.x;
    float4 v = ((const float4*)hr)[t];

    float s = v.x + v.y + v.z + v.w;
#pragma unroll
    for (int o = 16; o; o >>= 1) s += __shfl_xor_sync(0xffffffffu, s, o);
    __shared__ float s1[4];
    __shared__ float s2[4];
    if ((t & 31) == 0) s1[t >> 5] = s;
    __syncthreads();
    float mu = (s1[0] + s1[1] + s1[2] + s1[3]) * (1.f / CC);

    float dx = v.x - mu, dy = v.y - mu, dz = v.z - mu, dw = v.w - mu;
    float q = dx * dx + dy * dy + dz * dz + dw * dw;
#pragma unroll
    for (int o = 16; o; o >>= 1) q += __shfl_xor_sync(0xffffffffu, q, o);
    if ((t & 31) == 0) s2[t >> 5] = q;
    __syncthreads();
    float var = (s2[0] + s2[1] + s2[2] + s2[3]) * (1.f / CC);
    float inv = rsqrtf(var + LN_EPS);

    float4 g = ((const float4*)gamma)[t];
    float4 b = ((const float4*)beta)[t];
    float4 o4;
    o4.x = dx * inv * g.x + b.x;
    o4.y = dy * inv * g.y + b.y;
    o4.z = dz * inv * g.z + b.z;
    o4.w = dw * inv * g.w + b.w;
    ((float4*)(out + (size_t)blockIdx.x * CC))[t] = o4;
}

// ---------------- launch ----------------
extern "C" void kernel_launch(void* const* d_in, const int* in_sizes, int n_in,
                              void* d_out, int out_size) {
    const float* x     = (const float*)d_in[0];
    const float* Wq    = (const float*)d_in[1];
    const float* bq    = (const float*)d_in[2];
    const float* Wk    = (const float*)d_in[3];
    const float* bk    = (const float*)d_in[4];
    const float* Wv    = (const float*)d_in[5];
    const float* bv    = (const float*)d_in[6];
    const float* Wo    = (const float*)d_in[7];
    const float* bo    = (const float*)d_in[8];
    const float* gamma = (const float*)d_in[9];
    const float* beta  = (const float*)d_in[10];

    float* out = (float*)d_out;
    float* attn = out;                                   // [B,T,T]
    float* final_out = out + (size_t)BB * TT * TT;       // [B,T,C]

    float *resid, *q, *k, *v, *att;
    cudaGetSymbolAddress((void**)&resid, g_resid);
    cudaGetSymbolAddress((void**)&q, g_q);
    cudaGetSymbolAddress((void**)&k, g_k);
    cudaGetSymbolAddress((void**)&v, g_v);
    cudaGetSymbolAddress((void**)&att, g_att);

    // 1. transpose x -> resid
    transpose_kernel<<<dim3(TT / 32, CC / 32, BB), dim3(32, 8)>>>(x, resid);

    // 2. QKV projections: [B*T, C] @ [C, E] + bias
    {
        dim3 grid(EE / 128, (BB * TT) / 128, 1);
        sgemm<false, 1><<<grid, 256>>>(resid, Wq, bq, nullptr, q, CC, CC, EE, EE, 0, 0, 0);
        sgemm<false, 1><<<grid, 256>>>(resid, Wk, bk, nullptr, k, CC, CC, EE, EE, 0, 0, 0);
        sgemm<false, 1><<<grid, 256>>>(resid, Wv, bv, nullptr, v, CC, CC, EE, EE, 0, 0, 0);
    }

    // 3. energy = q @ k^T  -> attn region of d_out (raw logits)
    {
        dim3 grid(TT / 128, TT / 128, BB);
        sgemm<true, 0><<<grid, 256>>>(q, k, nullptr, nullptr, attn,
                                      EE, EE, EE, TT,
                                      (size_t)TT * EE, (size_t)TT * EE, (size_t)TT * TT);
    }

    // 4. softmax in place over last dim
    softmax_kernel<<<BB * TT, 256>>>(attn);

    // 5. attended = attn @ v
    {
        dim3 grid(EE / 128, TT / 128, BB);
        sgemm<false, 0><<<grid, 256>>>(attn, v, nullptr, nullptr, att,
                                       TT, TT, EE, EE,
                                       (size_t)TT * TT, (size_t)TT * EE, (size_t)TT * EE);
    }

    // 6. h = attended @ Wo + bo + resid   (h reuses g_q)
    {
        dim3 grid(CC / 128, (BB * TT) / 128, 1);
        sgemm<false, 2><<<grid, 256>>>(att, Wo, bo, resid, q, EE, EE, CC, CC, 0, 0, 0);
    }

    // 7. LayerNorm -> final output region
    ln_kernel<<<BB * TT, 128>>>(q, gamma, beta, final_out);
}

// round 4
// speedup vs baseline: 2.1651x; 2.1651x over previous
#include <cuda_runtime.h>
#include <cuda_bf16.h>
#include <cstdint>

#define BB 8
#define CC 512
#define TT 2048
#define EE 512
#define LN_EPS 1e-5f

typedef __nv_bfloat16 bf16;

// ------------------------------------------------------------------
// scratch (device globals — allocation-free rule)
// ------------------------------------------------------------------
__device__ float g_resid[BB * TT * CC];
__device__ bf16  g_resid_h[BB * TT * CC];
__device__ bf16  g_resid_l[BB * TT * CC];
__device__ bf16  g_q_h[BB * TT * EE];
__device__ bf16  g_q_l[BB * TT * EE];
__device__ bf16  g_k_h[BB * TT * EE];
__device__ bf16  g_k_l[BB * TT * EE];
__device__ bf16  g_vt_h[BB * EE * TT];   // v transposed: [B][E][T]
__device__ bf16  g_vt_l[BB * EE * TT];
__device__ bf16  g_attn_h[(size_t)BB * TT * TT];
__device__ bf16  g_attn_l[(size_t)BB * TT * TT];
__device__ bf16  g_att_h[BB * TT * EE];
__device__ bf16  g_att_l[BB * TT * EE];
__device__ float g_h[BB * TT * CC];
__device__ bf16  g_WqT_h[EE * CC], g_WqT_l[EE * CC];  // [E,C] = Wq^T
__device__ bf16  g_WkT_h[EE * CC], g_WkT_l[EE * CC];
__device__ bf16  g_WvT_h[EE * CC], g_WvT_l[EE * CC];
__device__ bf16  g_WoT_h[CC * EE], g_WoT_l[CC * EE];  // [C,E] = Wo^T

// ------------------------------------------------------------------
// low-level helpers (family-portable ISA only: ldmatrix / mma.sync / cp.async)
// ------------------------------------------------------------------
__device__ __forceinline__ uint32_t smem_u32(const void* p) {
    uint32_t a;
    asm("{ .reg .u64 t; cvta.to.shared.u64 t, %1; cvt.u32.u64 %0, t; }" : "=r"(a) : "l"(p));
    return a;
}

__device__ __forceinline__ uint32_t swz64(uint32_t o) { return o ^ ((o >> 3) & 0x30); }

#define CP16(dst, src) \
    asm volatile("cp.async.cg.shared.global [%0], [%1], 16;" :: "r"(dst), "l"(src))
#define CP_COMMIT() asm volatile("cp.async.commit_group;" ::: "memory")
#define CP_WAIT(n)  asm volatile("cp.async.wait_group %0;" :: "n"(n) : "memory")

__device__ __forceinline__ void ldsm4(uint32_t* r, uint32_t addr) {
    asm volatile("ldmatrix.sync.aligned.m8n8.x4.shared.b16 {%0,%1,%2,%3}, [%4];"
                 : "=r"(r[0]), "=r"(r[1]), "=r"(r[2]), "=r"(r[3]) : "r"(addr));
}

__device__ __forceinline__ void mma_bf16(float* c, const uint32_t* a,
                                         uint32_t b0, uint32_t b1) {
    asm volatile(
        "mma.sync.aligned.m16n8k16.row.col.f32.bf16.bf16.f32 "
        "{%0,%1,%2,%3}, {%4,%5,%6,%7}, {%8,%9}, {%0,%1,%2,%3};"
        : "+f"(c[0]), "+f"(c[1]), "+f"(c[2]), "+f"(c[3])
        : "r"(a[0]), "r"(a[1]), "r"(a[2]), "r"(a[3]), "r"(b0), "r"(b1));
}

__device__ __forceinline__ void split2(float v, bf16& h, bf16& l) {
    h = __float2bfloat16(v);
    l = __float2bfloat16(v - __bfloat162float(h));
}

// ------------------------------------------------------------------
// HMMA GEMM: D[128m x 128n] = (Ah+Al)·(Bh+Bl)^T  (3-term split)
// A row-major [M,K], B row-major [N,K]. BK=32, cp.async double buffer.
// ------------------------------------------------------------------
#define TILE_B (128 * 32 * 2)          // 8 KB per bf16 tile
#define CHUNK_B (4 * TILE_B)           // 32 KB (Ah,Al,Bh,Bl)
#define GEMM_SMEM_REQ 69632            // max(2*CHUNK_B, 128*129*4 stage)

enum { EPI_F32 = 0, EPI_BIAS_SPLIT = 1, EPI_BIAS_SPLIT_T = 2, EPI_SPLIT = 3, EPI_F32_BIAS_RES = 4 };

template <int EPI>
__global__ __launch_bounds__(256)
void hmma_gemm(const bf16* __restrict__ Ah, const bf16* __restrict__ Al, int ldA, size_t sA,
               const bf16* __restrict__ Bh, const bf16* __restrict__ Bl, int ldB, size_t sB,
               const float* __restrict__ bias, const float* __restrict__ res,
               float* __restrict__ Cf, bf16* __restrict__ Ch, bf16* __restrict__ Cl,
               int ldc, size_t sC, int K) {
    extern __shared__ char sm[];
    uint32_t smu = smem_u32(sm);

    const int tid = threadIdx.x;
    const int w = tid >> 5, lane = tid & 31;
    const int bz = blockIdx.z;
    const int m0 = blockIdx.y * 128;
    const int n0 = blockIdx.x * 128;

    const bf16* pAh = Ah + (size_t)bz * sA + (size_t)m0 * ldA;
    const bf16* pAl = Al + (size_t)bz * sA + (size_t)m0 * ldA;
    const bf16* pBh = Bh + (size_t)bz * sB + (size_t)n0 * ldB;
    const bf16* pBl = Bl + (size_t)bz * sB + (size_t)n0 * ldB;

    // loader: 2048 16B segments per chunk / 256 threads = 8 cp.async each
    auto load_chunk = [&](int buf, int k0) {
        uint32_t base = smu + (uint32_t)buf * CHUNK_B;
#pragma unroll
        for (int j = 0; j < 2; j++) {
            int v = tid + j * 256;
            int row = v >> 2, cs = v & 3;
            uint32_t off = swz64((uint32_t)(row * 64 + cs * 16));
            const bf16* ah = pAh + (size_t)row * ldA + k0 + cs * 8;
            const bf16* al = pAl + (size_t)row * ldA + k0 + cs * 8;
            const bf16* bh = pBh + (size_t)row * ldB + k0 + cs * 8;
            const bf16* bl = pBl + (size_t)row * ldB + k0 + cs * 8;
            CP16(base + 0 * TILE_B + off, ah);
            CP16(base + 1 * TILE_B + off, al);
            CP16(base + 2 * TILE_B + off, bh);
            CP16(base + 3 * TILE_B + off, bl);
        }
    };

    // warp layout: 4 (m) x 2 (n); warp tile 32 x 64
    const int wm = w >> 1, wn = w & 1;
    // ldmatrix lane addressing
    const int lr = lane & 7;
    const int r8 = (lane >> 3) & 1;
    const int chi = lane >> 4;

    uint32_t offA[2][2], offB[4][2];
#pragma unroll
    for (int mt = 0; mt < 2; mt++)
#pragma unroll
        for (int ks = 0; ks < 2; ks++)
            offA[mt][ks] = swz64((uint32_t)((wm * 32 + mt * 16 + r8 * 8 + lr) * 64 + (2 * ks + chi) * 16));
#pragma unroll
    for (int pt = 0; pt < 4; pt++)
#pragma unroll
        for (int ks = 0; ks < 2; ks++)
            offB[pt][ks] = swz64((uint32_t)((wn * 64 + pt * 16 + r8 * 8 + lr) * 64 + (2 * ks + chi) * 16));

    float acc[2][8][4];
#pragma unroll
    for (int i = 0; i < 2; i++)
#pragma unroll
        for (int j = 0; j < 8; j++)
#pragma unroll
            for (int q = 0; q < 4; q++) acc[i][j][q] = 0.f;

    const int nch = K / 32;
    load_chunk(0, 0);
    CP_COMMIT();

    for (int c = 0; c < nch; c++) {
        if (c + 1 < nch) {
            load_chunk((c + 1) & 1, (c + 1) * 32);
            CP_COMMIT();
            CP_WAIT(1);
        } else {
            CP_WAIT(0);
        }
        __syncthreads();

        uint32_t bu = smu + (uint32_t)(c & 1) * CHUNK_B;
#pragma unroll
        for (int ks = 0; ks < 2; ks++) {
            uint32_t afh[2][4], afl[2][4], bfh[4][4], bfl[4][4];
#pragma unroll
            for (int mt = 0; mt < 2; mt++) {
                ldsm4(afh[mt], bu + 0 * TILE_B + offA[mt][ks]);
                ldsm4(afl[mt], bu + 1 * TILE_B + offA[mt][ks]);
            }
#pragma unroll
            for (int pt = 0; pt < 4; pt++) {
                ldsm4(bfh[pt], bu + 2 * TILE_B + offB[pt][ks]);
                ldsm4(bfl[pt], bu + 3 * TILE_B + offB[pt][ks]);
            }
#pragma unroll
            for (int mt = 0; mt < 2; mt++) {
#pragma unroll
                for (int pt = 0; pt < 4; pt++) {
                    // n-tile 2*pt uses b regs (0,2); 2*pt+1 uses (1,3)
                    mma_bf16(acc[mt][2 * pt + 0], afh[mt], bfh[pt][0], bfh[pt][2]);
                    mma_bf16(acc[mt][2 * pt + 0], afh[mt], bfl[pt][0], bfl[pt][2]);
                    mma_bf16(acc[mt][2 * pt + 0], afl[mt], bfh[pt][0], bfh[pt][2]);
                    mma_bf16(acc[mt][2 * pt + 1], afh[mt], bfh[pt][1], bfh[pt][3]);
                    mma_bf16(acc[mt][2 * pt + 1], afh[mt], bfl[pt][1], bfl[pt][3]);
                    mma_bf16(acc[mt][2 * pt + 1], afl[mt], bfh[pt][1], bfh[pt][3]);
                }
            }
        }
        __syncthreads();   // buffer will be overwritten by loads issued next iter
    }

    // ---- epilogue: accumulators -> staged smem [128][129] fp32 -> gmem ----
    float* st = (float*)sm;
    {
        int g = lane >> 2, t4 = lane & 3;
#pragma unroll
        for (int mt = 0; mt < 2; mt++)
#pragma unroll
            for (int nt = 0; nt < 8; nt++) {
                int r = wm * 32 + mt * 16 + g;
                int ccol = wn * 64 + nt * 8 + 2 * t4;
                st[r * 129 + ccol]           = acc[mt][nt][0];
                st[r * 129 + ccol + 1]       = acc[mt][nt][1];
                st[(r + 8) * 129 + ccol]     = acc[mt][nt][2];
                st[(r + 8) * 129 + ccol + 1] = acc[mt][nt][3];
            }
    }
    __syncthreads();

    if (EPI == EPI_BIAS_SPLIT_T) {
        // transposed split store: dest vt[b][e][t]
#pragma unroll 4
        for (int it = 0; it < 16; it++) {
            int col = w + 8 * it;
            float bv = bias[n0 + col];
#pragma unroll
            for (int j = 0; j < 4; j++) {
                int row = lane + 32 * j;
                float v = st[row * 129 + col] + bv;
                size_t m = (size_t)m0 + row;
                int bb_ = (int)(m / TT);
                int t = (int)(m % TT);
                size_t off = ((size_t)bb_ * EE + (n0 + col)) * TT + t;
                bf16 h, l; split2(v, h, l);
                Ch[off] = h;
                Cl[off] = l;
            }
        }
    } else {
        float bv[4];
#pragma unroll
        for (int cb = 0; cb < 4; cb++)
            bv[cb] = (EPI == EPI_BIAS_SPLIT || EPI == EPI_F32_BIAS_RES) ? bias[n0 + lane + 32 * cb] : 0.f;

#pragma unroll 2
        for (int rr = 0; rr < 16; rr++) {
            int row = w * 16 + rr;
            size_t m = (size_t)m0 + row;
#pragma unroll
            for (int cb = 0; cb < 4; cb++) {
                int col = lane + 32 * cb;
                float v = st[row * 129 + col] + bv[cb];
                size_t off = (size_t)bz * sC + m * ldc + n0 + col;
                if (EPI == EPI_F32) {
                    Cf[off] = v;
                } else if (EPI == EPI_F32_BIAS_RES) {
                    Cf[off] = v + res[m * ldc + n0 + col];
                } else {  // split row-major
                    bf16 h, l; split2(v, h, l);
                    Ch[off] = h;
                    Cl[off] = l;
                }
            }
        }
    }
}

// ------------------------------------------------------------------
// transpose + split: x[B,C,T] -> resid[B,T,C] (fp32 + hi/lo bf16)
// ------------------------------------------------------------------
__global__ __launch_bounds__(256)
void transpose_split(const float* __restrict__ x, float* __restrict__ r,
                     bf16* __restrict__ rh, bf16* __restrict__ rl) {
    __shared__ float tile[32][33];
    int b = blockIdx.z;
    int t0 = blockIdx.x * 32;
    int c0 = blockIdx.y * 32;
    const float* xb = x + (size_t)b * CC * TT;
    size_t ob = (size_t)b * TT * CC;
    int tx = threadIdx.x, ty = threadIdx.y;
#pragma unroll
    for (int i = ty; i < 32; i += 8)
        tile[i][tx] = xb[(size_t)(c0 + i) * TT + t0 + tx];
    __syncthreads();
#pragma unroll
    for (int i = ty; i < 32; i += 8) {
        float v = tile[tx][i];
        size_t off = ob + (size_t)(t0 + i) * CC + c0 + tx;
        r[off] = v;
        bf16 h, l; split2(v, h, l);
        rh[off] = h;
        rl[off] = l;
    }
}

// W [512,512] -> W^T hi/lo [512,512]
__global__ __launch_bounds__(256)
void wsplit(const float* __restrict__ W, bf16* __restrict__ Th, bf16* __restrict__ Tl) {
    __shared__ float tile[32][33];
    int k0 = blockIdx.y * 32, n0 = blockIdx.x * 32;
    int tx = threadIdx.x, ty = threadIdx.y;
#pragma unroll
    for (int i = ty; i < 32; i += 8)
        tile[i][tx] = W[(size_t)(k0 + i) * 512 + n0 + tx];
    __syncthreads();
#pragma unroll
    for (int i = ty; i < 32; i += 8) {
        float v = tile[tx][i];  // W[k0+tx][n0+i]
        size_t off = (size_t)(n0 + i) * 512 + k0 + tx;
        bf16 h, l; split2(v, h, l);
        Th[off] = h;
        Tl[off] = l;
    }
}

// ------------------------------------------------------------------
// softmax (in-place fp32) + emit hi/lo bf16
// ------------------------------------------------------------------
__global__ __launch_bounds__(256)
void softmax_split(float* __restrict__ attn, bf16* __restrict__ ah, bf16* __restrict__ al) {
    size_t ro = (size_t)blockIdx.x * TT;
    float* row = attn + ro;
    int t = threadIdx.x;
    float vals[8];
    float m = -1e30f;
#pragma unroll
    for (int j = 0; j < 8; j++) {
        vals[j] = row[t + 256 * j];
        m = fmaxf(m, vals[j]);
    }
#pragma unroll
    for (int o = 16; o; o >>= 1) m = fmaxf(m, __shfl_xor_sync(0xffffffffu, m, o));
    __shared__ float smax[8], ssum[8];
    if ((t & 31) == 0) smax[t >> 5] = m;
    __syncthreads();
    float rm = smax[0];
#pragma unroll
    for (int i = 1; i < 8; i++) rm = fmaxf(rm, smax[i]);

    float s = 0.f;
#pragma unroll
    for (int j = 0; j < 8; j++) {
        vals[j] = expf(vals[j] - rm);
        s += vals[j];
    }
#pragma unroll
    for (int o = 16; o; o >>= 1) s += __shfl_xor_sync(0xffffffffu, s, o);
    if ((t & 31) == 0) ssum[t >> 5] = s;
    __syncthreads();
    float tot = 0.f;
#pragma unroll
    for (int i = 0; i < 8; i++) tot += ssum[i];
    float inv = 1.f / tot;

#pragma unroll
    for (int j = 0; j < 8; j++) {
        float v = vals[j] * inv;
        row[t + 256 * j] = v;
        bf16 h, l; split2(v, h, l);
        ah[ro + t + 256 * j] = h;
        al[ro + t + 256 * j] = l;
    }
}

// ------------------------------------------------------------------
// LayerNorm over C=512
// ------------------------------------------------------------------
__global__ __launch_bounds__(128)
void ln_kernel(const float* __restrict__ h, const float* __restrict__ gamma,
               const float* __restrict__ beta, float* __restrict__ out) {
    const float* hr = h + (size_t)blockIdx.x * CC;
    int t = threadIdx.x;
    float4 v = ((const float4*)hr)[t];

    float s = v.x + v.y + v.z + v.w;
#pragma unroll
    for (int o = 16; o; o >>= 1) s += __shfl_xor_sync(0xffffffffu, s, o);
    __shared__ float s1[4], s2[4];
    if ((t & 31) == 0) s1[t >> 5] = s;
    __syncthreads();
    float mu = (s1[0] + s1[1] + s1[2] + s1[3]) * (1.f / CC);

    float dx = v.x - mu, dy = v.y - mu, dz = v.z - mu, dw = v.w - mu;
    float q = dx * dx + dy * dy + dz * dz + dw * dw;
#pragma unroll
    for (int o = 16; o; o >>= 1) q += __shfl_xor_sync(0xffffffffu, q, o);
    if ((t & 31) == 0) s2[t >> 5] = q;
    __syncthreads();
    float var = (s2[0] + s2[1] + s2[2] + s2[3]) * (1.f / CC);
    float inv = rsqrtf(var + LN_EPS);

    float4 g = ((const float4*)gamma)[t];
    float4 b = ((const float4*)beta)[t];
    float4 o4;
    o4.x = dx * inv * g.x + b.x;
    o4.y = dy * inv * g.y + b.y;
    o4.z = dz * inv * g.z + b.z;
    o4.w = dw * inv * g.w + b.w;
    ((float4*)(out + (size_t)blockIdx.x * CC))[t] = o4;
}

// ------------------------------------------------------------------
// launch
// ------------------------------------------------------------------
extern "C" void kernel_launch(void* const* d_in, const int* in_sizes, int n_in,
                              void* d_out, int out_size) {
    const float* x     = (const float*)d_in[0];
    const float* Wq    = (const float*)d_in[1];
    const float* bq    = (const float*)d_in[2];
    const float* Wk    = (const float*)d_in[3];
    const float* bk    = (const float*)d_in[4];
    const float* Wv    = (const float*)d_in[5];
    const float* bv    = (const float*)d_in[6];
    const float* Wo    = (const float*)d_in[7];
    const float* bo    = (const float*)d_in[8];
    const float* gamma = (const float*)d_in[9];
    const float* beta  = (const float*)d_in[10];

    float* out = (float*)d_out;
    float* attn = out;
    float* final_out = out + (size_t)BB * TT * TT;

    float *resid, *hbuf;
    bf16 *rh, *rl, *qh, *ql, *kh, *kl, *vth, *vtl, *anh, *anl, *ath, *atl;
    bf16 *wqh, *wql, *wkh, *wkl, *wvh, *wvl, *woh, *wol;
    cudaGetSymbolAddress((void**)&resid, g_resid);
    cudaGetSymbolAddress((void**)&hbuf, g_h);
    cudaGetSymbolAddress((void**)&rh, g_resid_h);
    cudaGetSymbolAddress((void**)&rl, g_resid_l);
    cudaGetSymbolAddress((void**)&qh, g_q_h);
    cudaGetSymbolAddress((void**)&ql, g_q_l);
    cudaGetSymbolAddress((void**)&kh, g_k_h);
    cudaGetSymbolAddress((void**)&kl, g_k_l);
    cudaGetSymbolAddress((void**)&vth, g_vt_h);
    cudaGetSymbolAddress((void**)&vtl, g_vt_l);
    cudaGetSymbolAddress((void**)&anh, g_attn_h);
    cudaGetSymbolAddress((void**)&anl, g_attn_l);
    cudaGetSymbolAddress((void**)&ath, g_att_h);
    cudaGetSymbolAddress((void**)&atl, g_att_l);
    cudaGetSymbolAddress((void**)&wqh, g_WqT_h);
    cudaGetSymbolAddress((void**)&wql, g_WqT_l);
    cudaGetSymbolAddress((void**)&wkh, g_WkT_h);
    cudaGetSymbolAddress((void**)&wkl, g_WkT_l);
    cudaGetSymbolAddress((void**)&wvh, g_WvT_h);
    cudaGetSymbolAddress((void**)&wvl, g_WvT_l);
    cudaGetSymbolAddress((void**)&woh, g_WoT_h);
    cudaGetSymbolAddress((void**)&wol, g_WoT_l);

    cudaFuncSetAttribute(hmma_gemm<EPI_F32>,          cudaFuncAttributeMaxDynamicSharedMemorySize, GEMM_SMEM_REQ);
    cudaFuncSetAttribute(hmma_gemm<EPI_BIAS_SPLIT>,   cudaFuncAttributeMaxDynamicSharedMemorySize, GEMM_SMEM_REQ);
    cudaFuncSetAttribute(hmma_gemm<EPI_BIAS_SPLIT_T>, cudaFuncAttributeMaxDynamicSharedMemorySize, GEMM_SMEM_REQ);
    cudaFuncSetAttribute(hmma_gemm<EPI_SPLIT>,        cudaFuncAttributeMaxDynamicSharedMemorySize, GEMM_SMEM_REQ);
    cudaFuncSetAttribute(hmma_gemm<EPI_F32_BIAS_RES>, cudaFuncAttributeMaxDynamicSharedMemorySize, GEMM_SMEM_REQ);

    // 1. transpose + split
    transpose_split<<<dim3(TT / 32, CC / 32, BB), dim3(32, 8)>>>(x, resid, rh, rl);

    // 2. weight transpose + split (tiny)
    wsplit<<<dim3(16, 16), dim3(32, 8)>>>(Wq, wqh, wql);
    wsplit<<<dim3(16, 16), dim3(32, 8)>>>(Wk, wkh, wkl);
    wsplit<<<dim3(16, 16), dim3(32, 8)>>>(Wv, wvh, wvl);
    wsplit<<<dim3(16, 16), dim3(32, 8)>>>(Wo, woh, wol);

    // 3. QKV projections: [16384,512] x [512,512]^T (stored [E,C])
    {
        dim3 grid(EE / 128, (BB * TT) / 128, 1);
        hmma_gemm<EPI_BIAS_SPLIT><<<grid, 256, GEMM_SMEM_REQ>>>(
            rh, rl, CC, 0, wqh, wql, CC, 0, bq, nullptr,
            nullptr, qh, ql, EE, 0, CC);
        hmma_gemm<EPI_BIAS_SPLIT><<<grid, 256, GEMM_SMEM_REQ>>>(
            rh, rl, CC, 0, wkh, wkl, CC, 0, bk, nullptr,
            nullptr, kh, kl, EE, 0, CC);
        hmma_gemm<EPI_BIAS_SPLIT_T><<<grid, 256, GEMM_SMEM_REQ>>>(
            rh, rl, CC, 0, wvh, wvl, CC, 0, bv, nullptr,
            nullptr, vth, vtl, EE, 0, CC);
    }

    // 4. energy = q @ k^T -> fp32 logits in attn output region
    {
        dim3 grid(TT / 128, TT / 128, BB);
        hmma_gemm<EPI_F32><<<grid, 256, GEMM_SMEM_REQ>>>(
            qh, ql, EE, (size_t)TT * EE, kh, kl, EE, (size_t)TT * EE,
            nullptr, nullptr, attn, nullptr, nullptr, TT, (size_t)TT * TT, EE);
    }

    // 5. softmax in-place + split
    softmax_split<<<BB * TT, 256>>>(attn, anh, anl);

    // 6. attended = attn @ v   (B operand = v^T [E,T])
    {
        dim3 grid(EE / 128, TT / 128, BB);
        hmma_gemm<EPI_SPLIT><<<grid, 256, GEMM_SMEM_REQ>>>(
            anh, anl, TT, (size_t)TT * TT, vth, vtl, TT, (size_t)EE * TT,
            nullptr, nullptr, nullptr, ath, atl, EE, (size_t)TT * EE, TT);
    }

    // 7. h = attended @ Wo + bo + resid (fp32)
    {
        dim3 grid(CC / 128, (BB * TT) / 128, 1);
        hmma_gemm<EPI_F32_BIAS_RES><<<grid, 256, GEMM_SMEM_REQ>>>(
            ath, atl, EE, 0, woh, wol, EE, 0, bo, resid,
            hbuf, nullptr, nullptr, CC, 0, EE);
    }

    // 8. LayerNorm -> final output region
    ln_kernel<<<BB * TT, 128>>>(hbuf, gamma, beta, final_out);
}

// round 5
// speedup vs baseline: 2.3431x; 1.0822x over previous
#include <cuda_runtime.h>
#include <cuda_bf16.h>
#include <cstdint>

#define BB 8
#define CC 512
#define TT 2048
#define EE 512
#define LN_EPS 1e-5f

typedef __nv_bfloat16 bf16;

// ------------------------------------------------------------------
// scratch (device globals — allocation-free rule)
// ------------------------------------------------------------------
__device__ float g_resid[BB * TT * CC];
__device__ bf16  g_resid_h[BB * TT * CC];
__device__ bf16  g_resid_l[BB * TT * CC];
__device__ bf16  g_q_h[BB * TT * EE];
__device__ bf16  g_q_l[BB * TT * EE];
__device__ bf16  g_k_h[BB * TT * EE];
__device__ bf16  g_k_l[BB * TT * EE];
__device__ bf16  g_vt_h[BB * EE * TT];   // v transposed: [B][E][T]
__device__ bf16  g_vt_l[BB * EE * TT];
__device__ bf16  g_attn_h[(size_t)BB * TT * TT];
__device__ bf16  g_attn_l[(size_t)BB * TT * TT];
__device__ bf16  g_att_h[BB * TT * EE];
__device__ bf16  g_att_l[BB * TT * EE];
__device__ float g_h[BB * TT * CC];
__device__ bf16  g_WqT_h[EE * CC], g_WqT_l[EE * CC];  // [E,C] = Wq^T
__device__ bf16  g_WkT_h[EE * CC], g_WkT_l[EE * CC];
__device__ bf16  g_WvT_h[EE * CC], g_WvT_l[EE * CC];
__device__ bf16  g_WoT_h[CC * EE], g_WoT_l[CC * EE];  // [C,E] = Wo^T

// ------------------------------------------------------------------
// low-level helpers (family-portable ISA only: ldmatrix / mma.sync / cp.async)
// ------------------------------------------------------------------
__device__ __forceinline__ uint32_t smem_u32(const void* p) {
    uint32_t a;
    asm("{ .reg .u64 t; cvta.to.shared.u64 t, %1; cvt.u32.u64 %0, t; }" : "=r"(a) : "l"(p));
    return a;
}

__device__ __forceinline__ uint32_t swz64(uint32_t o) { return o ^ ((o >> 3) & 0x30); }

#define CP16(dst, src) \
    asm volatile("cp.async.cg.shared.global [%0], [%1], 16;" :: "r"(dst), "l"(src))
#define CP_COMMIT() asm volatile("cp.async.commit_group;" ::: "memory")
#define CP_WAIT(n)  asm volatile("cp.async.wait_group %0;" :: "n"(n) : "memory")

__device__ __forceinline__ void ldsm4(uint32_t* r, uint32_t addr) {
    asm volatile("ldmatrix.sync.aligned.m8n8.x4.shared.b16 {%0,%1,%2,%3}, [%4];"
                 : "=r"(r[0]), "=r"(r[1]), "=r"(r[2]), "=r"(r[3]) : "r"(addr));
}

__device__ __forceinline__ void mma_bf16(float* c, const uint32_t* a,
                                         uint32_t b0, uint32_t b1) {
    asm volatile(
        "mma.sync.aligned.m16n8k16.row.col.f32.bf16.bf16.f32 "
        "{%0,%1,%2,%3}, {%4,%5,%6,%7}, {%8,%9}, {%0,%1,%2,%3};"
        : "+f"(c[0]), "+f"(c[1]), "+f"(c[2]), "+f"(c[3])
        : "r"(a[0]), "r"(a[1]), "r"(a[2]), "r"(a[3]), "r"(b0), "r"(b1));
}

__device__ __forceinline__ void split2(float v, bf16& h, bf16& l) {
    h = __float2bfloat16(v);
    l = __float2bfloat16(v - __bfloat162float(h));
}

// ------------------------------------------------------------------
// HMMA GEMM: D[128m x 128n] = (Ah+Al)·(Bh+Bl)^T  (3-term split)
// A row-major [M,K], B row-major [N,K]. BK=32.
// 512 threads, 16 warps (8m x 2n), warp tile 16x64.
// 3-stage cp.async pipeline (96 KB smem).
// ------------------------------------------------------------------
#define TILE_B (128 * 32 * 2)          // 8 KB per bf16 tile
#define CHUNK_B (4 * TILE_B)           // 32 KB (Ah,Al,Bh,Bl)
#define NSTAGE 3
#define GEMM_SMEM_REQ (NSTAGE * CHUNK_B)   // 96 KB (epilogue stage 66KB reuses it)

enum { EPI_F32 = 0, EPI_BIAS_SPLIT = 1, EPI_BIAS_SPLIT_T = 2, EPI_SPLIT = 3, EPI_F32_BIAS_RES = 4 };

template <int EPI>
__global__ __launch_bounds__(512)
void hmma_gemm(const bf16* __restrict__ Ah, const bf16* __restrict__ Al, int ldA, size_t sA,
               const bf16* __restrict__ Bh, const bf16* __restrict__ Bl, int ldB, size_t sB,
               const float* __restrict__ bias, const float* __restrict__ res,
               float* __restrict__ Cf, bf16* __restrict__ Ch, bf16* __restrict__ Cl,
               int ldc, size_t sC, int K) {
    extern __shared__ char sm[];
    uint32_t smu = smem_u32(sm);

    const int tid = threadIdx.x;
    const int w = tid >> 5, lane = tid & 31;
    const int bz = blockIdx.z;
    const int m0 = blockIdx.y * 128;
    const int n0 = blockIdx.x * 128;

    const bf16* pAh = Ah + (size_t)bz * sA + (size_t)m0 * ldA;
    const bf16* pAl = Al + (size_t)bz * sA + (size_t)m0 * ldA;
    const bf16* pBh = Bh + (size_t)bz * sB + (size_t)n0 * ldB;
    const bf16* pBl = Bl + (size_t)bz * sB + (size_t)n0 * ldB;

    // loader: 512 segments per tile, 4 tiles, 512 threads -> 4 cp.async each
    const int lrow = tid >> 2, lcs = tid & 3;
    const uint32_t loff = swz64((uint32_t)(lrow * 64 + lcs * 16));
    auto load_chunk = [&](int buf, int k0) {
        uint32_t base = smu + (uint32_t)buf * CHUNK_B;
        const bf16* ah = pAh + (size_t)lrow * ldA + k0 + lcs * 8;
        const bf16* al = pAl + (size_t)lrow * ldA + k0 + lcs * 8;
        const bf16* bh = pBh + (size_t)lrow * ldB + k0 + lcs * 8;
        const bf16* bl = pBl + (size_t)lrow * ldB + k0 + lcs * 8;
        CP16(base + 0 * TILE_B + loff, ah);
        CP16(base + 1 * TILE_B + loff, al);
        CP16(base + 2 * TILE_B + loff, bh);
        CP16(base + 3 * TILE_B + loff, bl);
    };

    // warp layout: 8 (m) x 2 (n); warp tile 16 x 64
    const int wm = w >> 1, wn = w & 1;
    const int lr = lane & 7;
    const int r8 = (lane >> 3) & 1;
    const int chi = lane >> 4;

    uint32_t offA[2], offB[4][2];
#pragma unroll
    for (int ks = 0; ks < 2; ks++)
        offA[ks] = swz64((uint32_t)((wm * 16 + r8 * 8 + lr) * 64 + (2 * ks + chi) * 16));
#pragma unroll
    for (int pt = 0; pt < 4; pt++)
#pragma unroll
        for (int ks = 0; ks < 2; ks++)
            offB[pt][ks] = swz64((uint32_t)((wn * 64 + pt * 16 + r8 * 8 + lr) * 64 + (2 * ks + chi) * 16));

    float acc[8][4];
#pragma unroll
    for (int j = 0; j < 8; j++)
#pragma unroll
        for (int q = 0; q < 4; q++) acc[j][q] = 0.f;

    const int nch = K / 32;
    load_chunk(0, 0);
    CP_COMMIT();
    if (nch > 1) load_chunk(1, 32);
    CP_COMMIT();

    int buf = 0;
    for (int c = 0; c < nch; c++) {
        if (c + 2 < nch) {
            int fb = buf + 2;
            if (fb >= NSTAGE) fb -= NSTAGE;
            load_chunk(fb, (c + 2) * 32);
        }
        CP_COMMIT();          // always commit (possibly empty group) -> wait(2) is exact
        CP_WAIT(2);
        __syncthreads();

        uint32_t bu = smu + (uint32_t)buf * CHUNK_B;
#pragma unroll
        for (int ks = 0; ks < 2; ks++) {
            uint32_t afh[4], afl[4], bfh[4][4], bfl[4][4];
            ldsm4(afh, bu + 0 * TILE_B + offA[ks]);
            ldsm4(afl, bu + 1 * TILE_B + offA[ks]);
#pragma unroll
            for (int pt = 0; pt < 4; pt++) {
                ldsm4(bfh[pt], bu + 2 * TILE_B + offB[pt][ks]);
                ldsm4(bfl[pt], bu + 3 * TILE_B + offB[pt][ks]);
            }
#pragma unroll
            for (int pt = 0; pt < 4; pt++) {
                mma_bf16(acc[2 * pt + 0], afh, bfh[pt][0], bfh[pt][2]);
                mma_bf16(acc[2 * pt + 0], afh, bfl[pt][0], bfl[pt][2]);
                mma_bf16(acc[2 * pt + 0], afl, bfh[pt][0], bfh[pt][2]);
                mma_bf16(acc[2 * pt + 1], afh, bfh[pt][1], bfh[pt][3]);
                mma_bf16(acc[2 * pt + 1], afh, bfl[pt][1], bfl[pt][3]);
                mma_bf16(acc[2 * pt + 1], afl, bfh[pt][1], bfh[pt][3]);
            }
        }
        __syncthreads();   // buffer reused NSTAGE iterations later
        buf++;
        if (buf == NSTAGE) buf = 0;
    }

    // ---- epilogue: accumulators -> staged smem [128][129] fp32 -> gmem ----
    float* st = (float*)sm;
    {
        int g = lane >> 2, t4 = lane & 3;
        int r = wm * 16 + g;
#pragma unroll
        for (int nt = 0; nt < 8; nt++) {
            int ccol = wn * 64 + nt * 8 + 2 * t4;
            st[r * 129 + ccol]           = acc[nt][0];
            st[r * 129 + ccol + 1]       = acc[nt][1];
            st[(r + 8) * 129 + ccol]     = acc[nt][2];
            st[(r + 8) * 129 + ccol + 1] = acc[nt][3];
        }
    }
    __syncthreads();

    if (EPI == EPI_BIAS_SPLIT_T) {
        // transposed split store: dest vt[b][e][t]
#pragma unroll 4
        for (int it = 0; it < 8; it++) {
            int col = w + 16 * it;
            float bv = bias[n0 + col];
#pragma unroll
            for (int j = 0; j < 4; j++) {
                int row = lane + 32 * j;
                float v = st[row * 129 + col] + bv;
                size_t m = (size_t)m0 + row;
                int bb_ = (int)(m / TT);
                int t = (int)(m % TT);
                size_t off = ((size_t)bb_ * EE + (n0 + col)) * TT + t;
                bf16 h, l; split2(v, h, l);
                Ch[off] = h;
                Cl[off] = l;
            }
        }
    } else {
        float bv[4];
#pragma unroll
        for (int cb = 0; cb < 4; cb++)
            bv[cb] = (EPI == EPI_BIAS_SPLIT || EPI == EPI_F32_BIAS_RES) ? bias[n0 + lane + 32 * cb] : 0.f;

#pragma unroll 2
        for (int rr = 0; rr < 8; rr++) {
            int row = w * 8 + rr;
            size_t m = (size_t)m0 + row;
#pragma unroll
            for (int cb = 0; cb < 4; cb++) {
                int col = lane + 32 * cb;
                float v = st[row * 129 + col] + bv[cb];
                size_t off = (size_t)bz * sC + m * ldc + n0 + col;
                if (EPI == EPI_F32) {
                    Cf[off] = v;
                } else if (EPI == EPI_F32_BIAS_RES) {
                    Cf[off] = v + res[m * ldc + n0 + col];
                } else {  // split row-major
                    bf16 h, l; split2(v, h, l);
                    Ch[off] = h;
                    Cl[off] = l;
                }
            }
        }
    }
}

// ------------------------------------------------------------------
// transpose + split: x[B,C,T] -> resid[B,T,C] (fp32 + hi/lo bf16)
// ------------------------------------------------------------------
__global__ __launch_bounds__(256)
void transpose_split(const float* __restrict__ x, float* __restrict__ r,
                     bf16* __restrict__ rh, bf16* __restrict__ rl) {
    __shared__ float tile[32][33];
    int b = blockIdx.z;
    int t0 = blockIdx.x * 32;
    int c0 = blockIdx.y * 32;
    const float* xb = x + (size_t)b * CC * TT;
    size_t ob = (size_t)b * TT * CC;
    int tx = threadIdx.x, ty = threadIdx.y;
#pragma unroll
    for (int i = ty; i < 32; i += 8)
        tile[i][tx] = xb[(size_t)(c0 + i) * TT + t0 + tx];
    __syncthreads();
#pragma unroll
    for (int i = ty; i < 32; i += 8) {
        float v = tile[tx][i];
        size_t off = ob + (size_t)(t0 + i) * CC + c0 + tx;
        r[off] = v;
        bf16 h, l; split2(v, h, l);
        rh[off] = h;
        rl[off] = l;
    }
}

// W [512,512] -> W^T hi/lo [512,512]
__global__ __launch_bounds__(256)
void wsplit(const float* __restrict__ W, bf16* __restrict__ Th, bf16* __restrict__ Tl) {
    __shared__ float tile[32][33];
    int k0 = blockIdx.y * 32, n0 = blockIdx.x * 32;
    int tx = threadIdx.x, ty = threadIdx.y;
#pragma unroll
    for (int i = ty; i < 32; i += 8)
        tile[i][tx] = W[(size_t)(k0 + i) * 512 + n0 + tx];
    __syncthreads();
#pragma unroll
    for (int i = ty; i < 32; i += 8) {
        float v = tile[tx][i];  // W[k0+tx][n0+i]
        size_t off = (size_t)(n0 + i) * 512 + k0 + tx;
        bf16 h, l; split2(v, h, l);
        Th[off] = h;
        Tl[off] = l;
    }
}

// ------------------------------------------------------------------
// softmax (in-place fp32) + emit hi/lo bf16
// ------------------------------------------------------------------
__global__ __launch_bounds__(256)
void softmax_split(float* __restrict__ attn, bf16* __restrict__ ah, bf16* __restrict__ al) {
    size_t ro = (size_t)blockIdx.x * TT;
    float* row = attn + ro;
    int t = threadIdx.x;
    float vals[8];
    float m = -1e30f;
#pragma unroll
    for (int j = 0; j < 8; j++) {
        vals[j] = row[t + 256 * j];
        m = fmaxf(m, vals[j]);
    }
#pragma unroll
    for (int o = 16; o; o >>= 1) m = fmaxf(m, __shfl_xor_sync(0xffffffffu, m, o));
    __shared__ float smax[8], ssum[8];
    if ((t & 31) == 0) smax[t >> 5] = m;
    __syncthreads();
    float rm = smax[0];
#pragma unroll
    for (int i = 1; i < 8; i++) rm = fmaxf(rm, smax[i]);

    float s = 0.f;
#pragma unroll
    for (int j = 0; j < 8; j++) {
        vals[j] = expf(vals[j] - rm);
        s += vals[j];
    }
#pragma unroll
    for (int o = 16; o; o >>= 1) s += __shfl_xor_sync(0xffffffffu, s, o);
    if ((t & 31) == 0) ssum[t >> 5] = s;
    __syncthreads();
    float tot = 0.f;
#pragma unroll
    for (int i = 0; i < 8; i++) tot += ssum[i];
    float inv = 1.f / tot;

#pragma unroll
    for (int j = 0; j < 8; j++) {
        float v = vals[j] * inv;
        row[t + 256 * j] = v;
        bf16 h, l; split2(v, h, l);
        ah[ro + t + 256 * j] = h;
        al[ro + t + 256 * j] = l;
    }
}

// ------------------------------------------------------------------
// LayerNorm over C=512
// ------------------------------------------------------------------
__global__ __launch_bounds__(128)
void ln_kernel(const float* __restrict__ h, const float* __restrict__ gamma,
               const float* __restrict__ beta, float* __restrict__ out) {
    const float* hr = h + (size_t)blockIdx.x * CC;
    int t = threadIdx.x;
    float4 v = ((const float4*)hr)[t];

    float s = v.x + v.y + v.z + v.w;
#pragma unroll
    for (int o = 16; o; o >>= 1) s += __shfl_xor_sync(0xffffffffu, s, o);
    __shared__ float s1[4], s2[4];
    if ((t & 31) == 0) s1[t >> 5] = s;
    __syncthreads();
    float mu = (s1[0] + s1[1] + s1[2] + s1[3]) * (1.f / CC);

    float dx = v.x - mu, dy = v.y - mu, dz = v.z - mu, dw = v.w - mu;
    float q = dx * dx + dy * dy + dz * dz + dw * dw;
#pragma unroll
    for (int o = 16; o; o >>= 1) q += __shfl_xor_sync(0xffffffffu, q, o);
    if ((t & 31) == 0) s2[t >> 5] = q;
    __syncthreads();
    float var = (s2[0] + s2[1] + s2[2] + s2[3]) * (1.f / CC);
    float inv = rsqrtf(var + LN_EPS);

    float4 g = ((const float4*)gamma)[t];
    float4 b = ((const float4*)beta)[t];
    float4 o4;
    o4.x = dx * inv * g.x + b.x;
    o4.y = dy * inv * g.y + b.y;
    o4.z = dz * inv * g.z + b.z;
    o4.w = dw * inv * g.w + b.w;
    ((float4*)(out + (size_t)blockIdx.x * CC))[t] = o4;
}

// ------------------------------------------------------------------
// launch
// ------------------------------------------------------------------
extern "C" void kernel_launch(void* const* d_in, const int* in_sizes, int n_in,
                              void* d_out, int out_size) {
    const float* x     = (const float*)d_in[0];
    const float* Wq    = (const float*)d_in[1];
    const float* bq    = (const float*)d_in[2];
    const float* Wk    = (const float*)d_in[3];
    const float* bk    = (const float*)d_in[4];
    const float* Wv    = (const float*)d_in[5];
    const float* bv    = (const float*)d_in[6];
    const float* Wo    = (const float*)d_in[7];
    const float* bo    = (const float*)d_in[8];
    const float* gamma = (const float*)d_in[9];
    const float* beta  = (const float*)d_in[10];

    float* out = (float*)d_out;
    float* attn = out;
    float* final_out = out + (size_t)BB * TT * TT;

    float *resid, *hbuf;
    bf16 *rh, *rl, *qh, *ql, *kh, *kl, *vth, *vtl, *anh, *anl, *ath, *atl;
    bf16 *wqh, *wql, *wkh, *wkl, *wvh, *wvl, *woh, *wol;
    cudaGetSymbolAddress((void**)&resid, g_resid);
    cudaGetSymbolAddress((void**)&hbuf, g_h);
    cudaGetSymbolAddress((void**)&rh, g_resid_h);
    cudaGetSymbolAddress((void**)&rl, g_resid_l);
    cudaGetSymbolAddress((void**)&qh, g_q_h);
    cudaGetSymbolAddress((void**)&ql, g_q_l);
    cudaGetSymbolAddress((void**)&kh, g_k_h);
    cudaGetSymbolAddress((void**)&kl, g_k_l);
    cudaGetSymbolAddress((void**)&vth, g_vt_h);
    cudaGetSymbolAddress((void**)&vtl, g_vt_l);
    cudaGetSymbolAddress((void**)&anh, g_attn_h);
    cudaGetSymbolAddress((void**)&anl, g_attn_l);
    cudaGetSymbolAddress((void**)&ath, g_att_h);
    cudaGetSymbolAddress((void**)&atl, g_att_l);
    cudaGetSymbolAddress((void**)&wqh, g_WqT_h);
    cudaGetSymbolAddress((void**)&wql, g_WqT_l);
    cudaGetSymbolAddress((void**)&wkh, g_WkT_h);
    cudaGetSymbolAddress((void**)&wkl, g_WkT_l);
    cudaGetSymbolAddress((void**)&wvh, g_WvT_h);
    cudaGetSymbolAddress((void**)&wvl, g_WvT_l);
    cudaGetSymbolAddress((void**)&woh, g_WoT_h);
    cudaGetSymbolAddress((void**)&wol, g_WoT_l);

    cudaFuncSetAttribute(hmma_gemm<EPI_F32>,          cudaFuncAttributeMaxDynamicSharedMemorySize, GEMM_SMEM_REQ);
    cudaFuncSetAttribute(hmma_gemm<EPI_BIAS_SPLIT>,   cudaFuncAttributeMaxDynamicSharedMemorySize, GEMM_SMEM_REQ);
    cudaFuncSetAttribute(hmma_gemm<EPI_BIAS_SPLIT_T>, cudaFuncAttributeMaxDynamicSharedMemorySize, GEMM_SMEM_REQ);
    cudaFuncSetAttribute(hmma_gemm<EPI_SPLIT>,        cudaFuncAttributeMaxDynamicSharedMemorySize, GEMM_SMEM_REQ);
    cudaFuncSetAttribute(hmma_gemm<EPI_F32_BIAS_RES>, cudaFuncAttributeMaxDynamicSharedMemorySize, GEMM_SMEM_REQ);

    // 1. transpose + split
    transpose_split<<<dim3(TT / 32, CC / 32, BB), dim3(32, 8)>>>(x, resid, rh, rl);

    // 2. weight transpose + split (tiny)
    wsplit<<<dim3(16, 16), dim3(32, 8)>>>(Wq, wqh, wql);
    wsplit<<<dim3(16, 16), dim3(32, 8)>>>(Wk, wkh, wkl);
    wsplit<<<dim3(16, 16), dim3(32, 8)>>>(Wv, wvh, wvl);
    wsplit<<<dim3(16, 16), dim3(32, 8)>>>(Wo, woh, wol);

    // 3. QKV projections: [16384,512] x [512,512]^T (stored [E,C])
    {
        dim3 grid(EE / 128, (BB * TT) / 128, 1);
        hmma_gemm<EPI_BIAS_SPLIT><<<grid, 512, GEMM_SMEM_REQ>>>(
            rh, rl, CC, 0, wqh, wql, CC, 0, bq, nullptr,
            nullptr, qh, ql, EE, 0, CC);
        hmma_gemm<EPI_BIAS_SPLIT><<<grid, 512, GEMM_SMEM_REQ>>>(
            rh, rl, CC, 0, wkh, wkl, CC, 0, bk, nullptr,
            nullptr, kh, kl, EE, 0, CC);
        hmma_gemm<EPI_BIAS_SPLIT_T><<<grid, 512, GEMM_SMEM_REQ>>>(
            rh, rl, CC, 0, wvh, wvl, CC, 0, bv, nullptr,
            nullptr, vth, vtl, EE, 0, CC);
    }

    // 4. energy = q @ k^T -> fp32 logits in attn output region
    {
        dim3 grid(TT / 128, TT / 128, BB);
        hmma_gemm<EPI_F32><<<grid, 512, GEMM_SMEM_REQ>>>(
            qh, ql, EE, (size_t)TT * EE, kh, kl, EE, (size_t)TT * EE,
            nullptr, nullptr, attn, nullptr, nullptr, TT, (size_t)TT * TT, EE);
    }

    // 5. softmax in-place + split
    softmax_split<<<BB * TT, 256>>>(attn, anh, anl);

    // 6. attended = attn @ v   (B operand = v^T [E,T])
    {
        dim3 grid(EE / 128, TT / 128, BB);
        hmma_gemm<EPI_SPLIT><<<grid, 512, GEMM_SMEM_REQ>>>(
            anh, anl, TT, (size_t)TT * TT, vth, vtl, TT, (size_t)EE * TT,
            nullptr, nullptr, nullptr, ath, atl, EE, (size_t)TT * EE, TT);
    }

    // 7. h = attended @ Wo + bo + resid (fp32)
    {
        dim3 grid(CC / 128, (BB * TT) / 128, 1);
        hmma_gemm<EPI_F32_BIAS_RES><<<grid, 512, GEMM_SMEM_REQ>>>(
            ath, atl, EE, 0, woh, wol, EE, 0, bo, resid,
            hbuf, nullptr, nullptr, CC, 0, EE);
    }

    // 8. LayerNorm -> final output region
    ln_kernel<<<BB * TT, 128>>>(hbuf, gamma, beta, final_out);
}